// round 6
// baseline (speedup 1.0000x reference)
#include <cuda_runtime.h>
#include <cuda_bf16.h>
#include <cstdint>
#include <cstddef>

#define B_DIM   16384
#define IN_DIM  512
#define OUT_DIM 512
#define ORDER   10
#define K_TOT   (IN_DIM + IN_DIM * ORDER)   /* 5632 */

// Only W scratch (11.5 MB, L2-resident). A is generated in-GEMM from x.
__device__ float g_W[(size_t)OUT_DIM * K_TOT];

__device__ __forceinline__ float to_tf32(float x) {
    float r;
    asm("cvt.rna.tf32.f32 %0, %1;" : "=f"(r) : "f"(x));
    return r;
}

// ---------------------------------------------------------------------------
// Phase 0: pack W[n,0:512]=base_weight[n,:], W[n,512:5632]=cheby_weight[n,:,:]
// (the (OUT, IN*O) reshape is a pure view of the contiguous (OUT,IN,O) tensor).
// TF32-rounded once here so the GEMM consumes clean tf32 operands.
// ---------------------------------------------------------------------------
__global__ void build_W_kernel(const float* __restrict__ bw,
                               const float* __restrict__ cw) {
    const int row_f4 = K_TOT / 4;  // 1408 float4 per row
    int idx = blockIdx.x * blockDim.x + threadIdx.x;
    if (idx >= OUT_DIM * row_f4) return;
    int n = idx / row_f4;
    int k = (idx - n * row_f4) * 4;
    float4 v;
    if (k < IN_DIM) {
        v = __ldg((const float4*)(bw + (size_t)n * IN_DIM + k));
    } else {
        v = __ldg((const float4*)(cw + (size_t)n * (IN_DIM * ORDER) + (k - IN_DIM)));
    }
    v.x = to_tf32(v.x); v.y = to_tf32(v.y); v.z = to_tf32(v.z); v.w = to_tf32(v.w);
    *(float4*)(g_W + (size_t)n * K_TOT + k) = v;
}

// ---------------------------------------------------------------------------
// Fused GEMM: C[16384,512] = A(x)[16384,5632] @ W[512,5632]^T, tf32 mma.
// A generated on the fly. For C-row b, K-tile kt (BK=16):  s = kt>>5.
//   s==0:  A[b, col] = silu(x[b, col])
//   s>=1:  o2=s-1, m=10*b+o2, o=m>>14, b'=m&16383,
//          A[b, col] = 0.1 * T_o(x[b', col-512*s])
// (exact inverse of the reference's (O,B,IN)->(B,O*IN) reshape; /ORDER folded)
// 128x128 C tile, 256 threads (8 warps 2x4, 64x32/warp), m16n8k8 tf32 MMAs.
// W: 2-stage cp.async pipeline. A: register-double-buffered LDG->cheby->STS.
// Smem rows padded to 20 floats -> fragment LDS provably conflict-free
// ((20*gid+tg) mod 32 hits all 32 banks once per warp).
// ---------------------------------------------------------------------------
#define BM 128
#define BN 128
#define BK 16
#define LDSS 20                       /* smem row stride in floats (80B) */
#define STAGE_M (BM * LDSS)           /* 2560 floats per matrix per stage */
#define NTHREADS 256
#define NKT (K_TOT / BK)              /* 352 */

__device__ __forceinline__ void cp_async16(unsigned dst, const void* src) {
    asm volatile("cp.async.cg.shared.global [%0], [%1], 16;" :: "r"(dst), "l"(src));
}
__device__ __forceinline__ void cp_commit() {
    asm volatile("cp.async.commit_group;");
}

// source pointer + order for the A value at (row b, tile kt, col offset lcol).
// o = -1 encodes the silu segment.
__device__ __forceinline__ const float4* a_src(const float* __restrict__ x,
                                               int kt, int b, int lcol, int& o) {
    int s = kt >> 5;
    int col = ((kt & 31) << 4) + lcol;
    int row;
    if (s == 0) { row = b; o = -1; }
    else { int m = b * 10 + (s - 1); o = m >> 14; row = m & 16383; }
    return (const float4*)(x + (size_t)row * IN_DIM + col);
}

__device__ __forceinline__ float4 a_val(float4 xv, int o) {
    float4 r;
    if (o < 0) {                      // silu
        r.x = xv.x / (1.0f + __expf(-xv.x));
        r.y = xv.y / (1.0f + __expf(-xv.y));
        r.z = xv.z / (1.0f + __expf(-xv.z));
        r.w = xv.w / (1.0f + __expf(-xv.w));
    } else if (o == 0) {              // 0.1 * T_0
        r = make_float4(0.1f, 0.1f, 0.1f, 0.1f);
    } else {                          // 0.1 * T_o,  T_1 = x
        float4 tm = make_float4(1.f, 1.f, 1.f, 1.f);
        float4 tc = xv;
        for (int j = 2; j <= o; j++) {
            float4 t;
            t.x = 2.0f * xv.x * tc.x - tm.x;
            t.y = 2.0f * xv.y * tc.y - tm.y;
            t.z = 2.0f * xv.z * tc.z - tm.z;
            t.w = 2.0f * xv.w * tc.w - tm.w;
            tm = tc; tc = t;
        }
        r.x = 0.1f * tc.x; r.y = 0.1f * tc.y;
        r.z = 0.1f * tc.z; r.w = 0.1f * tc.w;
    }
    r.x = to_tf32(r.x); r.y = to_tf32(r.y);
    r.z = to_tf32(r.z); r.w = to_tf32(r.w);
    return r;
}

__global__ __launch_bounds__(NTHREADS, 2)
void gemm_fused_kernel(const float* __restrict__ x, float* __restrict__ C) {
    __shared__ __align__(16) float sm[2][2 * STAGE_M];   // [stage][A | W] = 40KB

    const int tid  = threadIdx.x;
    const int lane = tid & 31;
    const int wid  = tid >> 5;
    const int wm   = wid >> 2;        // 0..1 -> 64-row slab
    const int wn   = wid & 3;         // 0..3 -> 32-col slab
    const int gid  = lane >> 2;       // groupID (0..7)
    const int tg   = lane & 3;        // thread-in-group (0..3)

    const int bm = blockIdx.y * BM;
    const int bn = blockIdx.x * BN;

    // loader: rows lrow and lrow+64 of the tile, 4 cols at lcol
    const int lrow = tid >> 2;
    const int lcol = (tid & 3) << 2;
    const int b0 = bm + lrow;
    const int b1 = bm + lrow + 64;

    const float* Wb = g_W + (size_t)(bn + lrow) * K_TOT + lcol;
    const unsigned smem_u32 = (unsigned)__cvta_generic_to_shared(&sm[0][0]);
    const unsigned dW0 = smem_u32 + (unsigned)(STAGE_M + lrow * LDSS + lcol) * 4u;

    // ---- prologue: tile 0 into stage 0 ----
    {
        cp_async16(dW0,                   Wb);
        cp_async16(dW0 + 64u * LDSS * 4u, Wb + (size_t)64 * K_TOT);
        cp_commit();
        int o0, o1;
        const float4* p0 = a_src(x, 0, b0, lcol, o0);
        const float4* p1 = a_src(x, 0, b1, lcol, o1);
        float4 v0 = a_val(__ldg(p0), o0);
        float4 v1 = a_val(__ldg(p1), o1);
        *(float4*)(&sm[0][0] + lrow * LDSS + lcol)        = v0;
        *(float4*)(&sm[0][0] + (lrow + 64) * LDSS + lcol) = v1;
        asm volatile("cp.async.wait_group 0;");
    }
    __syncthreads();

    float acc[4][4][4] = {};
    float4 xr0, xr1;
    int on0 = 0, on1 = 0;

    for (int kt = 0; kt < NKT; kt++) {
        // prefetch tile kt+1: x -> registers (LDG), W -> smem (cp.async)
        if (kt + 1 < NKT) {
            const float4* p0 = a_src(x, kt + 1, b0, lcol, on0);
            const float4* p1 = a_src(x, kt + 1, b1, lcol, on1);
            xr0 = __ldg(p0);
            xr1 = __ldg(p1);
            const unsigned soff = (unsigned)((kt + 1) & 1) * (2u * STAGE_M * 4u);
            const float* Wk = Wb + (size_t)(kt + 1) * BK;
            cp_async16(dW0 + soff,                   Wk);
            cp_async16(dW0 + soff + 64u * LDSS * 4u, Wk + (size_t)64 * K_TOT);
            cp_commit();
        }

        // MMAs on tile kt
        const float* A_s = &sm[kt & 1][0];
        const float* W_s = A_s + STAGE_M;
        const int arow = wm * 64 + gid;
        const int bcol = wn * 32 + gid;

#pragma unroll
        for (int ks = 0; ks < 2; ks++) {
            const int k0 = ks * 8 + tg;
            unsigned a[4][4], b[4][2];
#pragma unroll
            for (int mi = 0; mi < 4; mi++) {
                const float* p = A_s + (arow + mi * 16) * LDSS + k0;
                a[mi][0] = __float_as_uint(p[0]);
                a[mi][1] = __float_as_uint(p[8 * LDSS]);
                a[mi][2] = __float_as_uint(p[4]);
                a[mi][3] = __float_as_uint(p[8 * LDSS + 4]);
            }
#pragma unroll
            for (int ni = 0; ni < 4; ni++) {
                const float* p = W_s + (bcol + ni * 8) * LDSS + k0;
                b[ni][0] = __float_as_uint(p[0]);
                b[ni][1] = __float_as_uint(p[4]);
            }
#pragma unroll
            for (int mi = 0; mi < 4; mi++)
#pragma unroll
                for (int ni = 0; ni < 4; ni++) {
                    asm volatile(
                        "mma.sync.aligned.m16n8k8.row.col.f32.tf32.tf32.f32 "
                        "{%0,%1,%2,%3}, {%4,%5,%6,%7}, {%8,%9}, {%0,%1,%2,%3};"
                        : "+f"(acc[mi][ni][0]), "+f"(acc[mi][ni][1]),
                          "+f"(acc[mi][ni][2]), "+f"(acc[mi][ni][3])
                        : "r"(a[mi][0]), "r"(a[mi][1]), "r"(a[mi][2]), "r"(a[mi][3]),
                          "r"(b[ni][0]), "r"(b[ni][1]));
                }
        }

        // produce A tile kt+1 from prefetched x, land W tile kt+1
        if (kt + 1 < NKT) {
            float4 v0 = a_val(xr0, on0);
            float4 v1 = a_val(xr1, on1);
            float* A_n = &sm[(kt + 1) & 1][0];
            *(float4*)(A_n + lrow * LDSS + lcol)        = v0;
            *(float4*)(A_n + (lrow + 64) * LDSS + lcol) = v1;
            asm volatile("cp.async.wait_group 0;");
        }
        __syncthreads();
    }

    // epilogue: c0,c1 at (row, 2*tg), c2,c3 at (row+8, 2*tg)
#pragma unroll
    for (int mi = 0; mi < 4; mi++) {
#pragma unroll
        for (int ni = 0; ni < 4; ni++) {
            const int row = bm + wm * 64 + mi * 16 + gid;
            const int col = bn + wn * 32 + ni * 8 + 2 * tg;
            *(float2*)(C + (size_t)row * OUT_DIM + col) =
                make_float2(acc[mi][ni][0], acc[mi][ni][1]);
            *(float2*)(C + (size_t)(row + 8) * OUT_DIM + col) =
                make_float2(acc[mi][ni][2], acc[mi][ni][3]);
        }
    }
}

// ---------------------------------------------------------------------------
extern "C" void kernel_launch(void* const* d_in, const int* in_sizes, int n_in,
                              void* d_out, int out_size) {
    // Identify inputs defensively by element count (all three are distinct).
    const float* x  = nullptr;
    const float* bw = nullptr;
    const float* cw = nullptr;
    for (int i = 0; i < n_in; i++) {
        if (in_sizes[i] == B_DIM * IN_DIM)                x  = (const float*)d_in[i];
        else if (in_sizes[i] == OUT_DIM * IN_DIM)         bw = (const float*)d_in[i];
        else if (in_sizes[i] == OUT_DIM * IN_DIM * ORDER) cw = (const float*)d_in[i];
    }
    float* out = (float*)d_out;

    {   // phase 0: weight pack (720896 float4)
        int total = OUT_DIM * (K_TOT / 4);
        build_W_kernel<<<(total + 255) / 256, 256>>>(bw, cw);
    }
    {   // phase 1: fused A-gen + TF32 tensor-core GEMM
        dim3 grid(OUT_DIM / BN, B_DIM / BM);   // (4, 128)
        gemm_fused_kernel<<<grid, NTHREADS>>>(x, out);
    }
}